// round 4
// baseline (speedup 1.0000x reference)
#include <cuda_runtime.h>
#include <cuda_fp16.h>

// ---------------------------------------------------------------------------
// GCN_JK_Concat: 3x GCNConv(sym-norm, self-loops) + JK concat + Linear
// N=100000, E=1600000, F_IN=128, H=64, F_OUT=64
// R4: fp16 message features (halves gather L2 traffic); g_val removed
// (norm recomputed from dis in gather; fill scatters only col); int4 count.
// ---------------------------------------------------------------------------

#define NMAX   100000
#define EMAX   1600000
#define NNZMAX (EMAX + NMAX)
#define NBSCAN 128

__device__ int     g_deg[NMAX];
__device__ float   g_dis[NMAX];
__device__ int     g_rowptr[NMAX + 1];
__device__ int     g_cursor[NMAX];
__device__ int     g_bsum[NBSCAN];
__device__ int     g_boff[NBSCAN];
__device__ int     g_col[NNZMAX];
__device__ __half2 g_hw[(size_t)NMAX * 32];   // fp16 transformed features
__device__ float   g_h1[(size_t)NMAX * 64];
__device__ float   g_h2[(size_t)NMAX * 64];
__device__ float   g_h3[(size_t)NMAX * 64];

// ---------------------------------------------------------------------------
__global__ void k_init_deg(int n) {
    int i = blockIdx.x * blockDim.x + threadIdx.x;
    if (i < n) g_deg[i] = 1;   // self-loop
}

// 4 edges per thread via int4 when e % 4 == 0 (true for E=1.6M)
__global__ void k_count4(const int* __restrict__ ei, int e) {
    int i = blockIdx.x * blockDim.x + threadIdx.x;
    int base = i * 4;
    if (base + 3 < e) {
        int4 d = *(const int4*)&ei[(size_t)e + base];
        atomicAdd(&g_deg[d.x], 1);
        atomicAdd(&g_deg[d.y], 1);
        atomicAdd(&g_deg[d.z], 1);
        atomicAdd(&g_deg[d.w], 1);
    } else {
        for (int j = base; j < e; j++)
            atomicAdd(&g_deg[ei[(size_t)e + j]], 1);
    }
}

// ---- 3-pass parallel scan ----
__global__ void __launch_bounds__(1024) k_scan_local(int n) {
    __shared__ int warpsum[32];
    int t = threadIdx.x;
    int lane = t & 31;
    int w = t >> 5;
    int i = blockIdx.x * 1024 + t;
    int v = (i < n) ? g_deg[i] : 0;
    int s = v;
    #pragma unroll
    for (int o = 1; o < 32; o <<= 1) {
        int x = __shfl_up_sync(0xffffffffu, s, o);
        if (lane >= o) s += x;
    }
    if (lane == 31) warpsum[w] = s;
    __syncthreads();
    if (w == 0) {
        int v2 = warpsum[lane];
        #pragma unroll
        for (int o = 1; o < 32; o <<= 1) {
            int x = __shfl_up_sync(0xffffffffu, v2, o);
            if (lane >= o) v2 += x;
        }
        warpsum[lane] = v2;
    }
    __syncthreads();
    int prefix = (w == 0) ? 0 : warpsum[w - 1];
    int incl = prefix + s;
    if (i < n) {
        g_rowptr[i] = incl - v;          // local exclusive
        g_dis[i] = rsqrtf((float)v);
    }
    if (t == 1023) g_bsum[blockIdx.x] = incl;
}

__global__ void __launch_bounds__(128) k_scan_bsums(int nb, int n) {
    int t = threadIdx.x;
    int lane = t & 31;
    int w = t >> 5;
    __shared__ int warpsum[4];
    int v = (t < nb) ? g_bsum[t] : 0;
    int s = v;
    #pragma unroll
    for (int o = 1; o < 32; o <<= 1) {
        int x = __shfl_up_sync(0xffffffffu, s, o);
        if (lane >= o) s += x;
    }
    if (lane == 31) warpsum[w] = s;
    __syncthreads();
    int pre = 0;
    for (int j = 0; j < w; j++) pre += warpsum[j];
    if (t < nb) g_boff[t] = pre + s - v;
    if (t == nb - 1) g_rowptr[n] = pre + s;
}

__global__ void __launch_bounds__(1024) k_scan_add(int n) {
    int i = blockIdx.x * 1024 + threadIdx.x;
    if (i < n) {
        int rp = g_rowptr[i] + g_boff[blockIdx.x];
        g_rowptr[i] = rp;
        g_cursor[i] = rp;
    }
}

// fill: scatter only col (norm is recomputed in gather)
__global__ void k_fill(const int* __restrict__ ei, int e, int n) {
    int i = blockIdx.x * blockDim.x + threadIdx.x;
    int s, d;
    if (i < e) {
        s = ei[i];
        d = ei[(size_t)e + i];
    } else if (i < e + n) {
        s = d = i - e;                  // self-loop
    } else {
        return;
    }
    int pos = atomicAdd(&g_cursor[d], 1);
    g_col[pos] = s;
}

// ---------------------------------------------------------------------------
// GEMM: 128 rows/block, 128 threads, 8x8 register tile, fma.rn.f32x2.
// ---------------------------------------------------------------------------
#define TR2 128
#define TK2 32

#define FMA2(acc, a, b) \
    asm("fma.rn.f32x2 %0, %1, %2, %0;" : "+l"(acc) : "l"(a), "l"(b))

__device__ __forceinline__ unsigned long long bcast2(float a) {
    unsigned long long r;
    asm("mov.b64 %0, {%1, %1};" : "=l"(r) : "f"(a));
    return r;
}

struct GemmSmem {
    float xs[TR2][TK2 + 5];   // stride 37: conflict-free scalar reads
    float ws[TK2][64 + 4];    // stride 68: aligned LDS.128, broadcast
};

__device__ __forceinline__ void gemm_tile_load_W(
    GemmSmem* sm, const float* __restrict__ W, int kk, int t)
{
    #pragma unroll
    for (int s = 0; s < 4; s++) {
        int slot = t + s * 128;
        int k = slot >> 4;
        int c4 = slot & 15;
        *(float4*)&sm->ws[k][c4 * 4] = *(const float4*)&W[(size_t)(kk + k) * 64 + c4 * 4];
    }
}

__device__ __forceinline__ void gemm_tile_load_A(
    GemmSmem* sm, const float* __restrict__ A, int K, int kk,
    int rowBase, int n, int t)
{
    #pragma unroll
    for (int s = 0; s < 8; s++) {
        int slot = t + s * 128;
        int r = slot >> 3;
        int k4 = slot & 7;
        int row = rowBase + r;
        float4 v = make_float4(0.f, 0.f, 0.f, 0.f);
        if (row < n) v = *(const float4*)&A[(size_t)row * K + kk + k4 * 4];
        sm->xs[r][k4 * 4 + 0] = v.x;
        sm->xs[r][k4 * 4 + 1] = v.y;
        sm->xs[r][k4 * 4 + 2] = v.z;
        sm->xs[r][k4 * 4 + 3] = v.w;
    }
}

__device__ __forceinline__ void gemm_tile_compute(
    GemmSmem* sm, int tx, int ty, unsigned long long acc[8][4])
{
    #pragma unroll
    for (int k = 0; k < TK2; k++) {
        ulonglong2 wA = *(const ulonglong2*)&sm->ws[k][8 * tx];
        ulonglong2 wB = *(const ulonglong2*)&sm->ws[k][8 * tx + 4];
        #pragma unroll
        for (int i = 0; i < 8; i++) {
            unsigned long long aa = bcast2(sm->xs[8 * ty + i][k]);
            FMA2(acc[i][0], aa, wA.x);
            FMA2(acc[i][1], aa, wA.y);
            FMA2(acc[i][2], aa, wB.x);
            FMA2(acc[i][3], aa, wB.y);
        }
    }
}

// transform GEMM writing fp16 messages
__global__ void __launch_bounds__(128) k_gemm2h(
    const float* __restrict__ A, int K,
    const float* __restrict__ W,
    __half2* __restrict__ out, int n)
{
    __shared__ GemmSmem sm;
    int t = threadIdx.x;
    int tx = t & 7, ty = t >> 3;
    int rowBase = blockIdx.x * TR2;
    unsigned long long acc[8][4] = {};

    for (int kk = 0; kk < K; kk += TK2) {
        gemm_tile_load_A(&sm, A, K, kk, rowBase, n, t);
        gemm_tile_load_W(&sm, W, kk, t);
        __syncthreads();
        gemm_tile_compute(&sm, tx, ty, acc);
        __syncthreads();
    }
    #pragma unroll
    for (int i = 0; i < 8; i++) {
        int row = rowBase + 8 * ty + i;
        if (row < n) {
            union { uint4 u; __half2 h[4]; } p;
            p.h[0] = __float22half2_rn(*(float2*)&acc[i][0]);
            p.h[1] = __float22half2_rn(*(float2*)&acc[i][1]);
            p.h[2] = __float22half2_rn(*(float2*)&acc[i][2]);
            p.h[3] = __float22half2_rn(*(float2*)&acc[i][3]);
            *(uint4*)&out[(size_t)row * 32 + 4 * tx] = p.u;
        }
    }
}

// Final GEMM on virtual concat [x | h1 | h2 | h3] (K=320) with bias, fp32 out.
__global__ void __launch_bounds__(128) k_gemm_cat2(
    const float* __restrict__ x,
    const float* __restrict__ Wl,
    const float* __restrict__ bl,
    float* __restrict__ out, int n)
{
    __shared__ GemmSmem sm;
    int t = threadIdx.x;
    int tx = t & 7, ty = t >> 3;
    int rowBase = blockIdx.x * TR2;
    unsigned long long acc[8][4] = {};

    for (int kk = 0; kk < 320; kk += TK2) {
        const float* src;
        int stride, koff;
        if (kk < 128)      { src = x;    stride = 128; koff = kk; }
        else if (kk < 192) { src = g_h1; stride = 64;  koff = kk - 128; }
        else if (kk < 256) { src = g_h2; stride = 64;  koff = kk - 192; }
        else               { src = g_h3; stride = 64;  koff = kk - 256; }

        gemm_tile_load_A(&sm, src, stride, koff, rowBase, n, t);
        gemm_tile_load_W(&sm, Wl, kk, t);
        __syncthreads();
        gemm_tile_compute(&sm, tx, ty, acc);
        __syncthreads();
    }
    float4 bv0 = *(const float4*)&bl[8 * tx];
    float4 bv1 = *(const float4*)&bl[8 * tx + 4];
    #pragma unroll
    for (int i = 0; i < 8; i++) {
        int row = rowBase + 8 * ty + i;
        if (row < n) {
            float2 f0 = *(float2*)&acc[i][0];
            float2 f1 = *(float2*)&acc[i][1];
            float2 f2 = *(float2*)&acc[i][2];
            float2 f3 = *(float2*)&acc[i][3];
            *(float4*)&out[(size_t)row * 64 + 8 * tx] =
                make_float4(f0.x + bv0.x, f0.y + bv0.y, f1.x + bv0.z, f1.y + bv0.w);
            *(float4*)&out[(size_t)row * 64 + 8 * tx + 4] =
                make_float4(f2.x + bv1.x, f2.y + bv1.y, f3.x + bv1.z, f3.y + bv1.w);
        }
    }
}

// ---------------------------------------------------------------------------
// Aggregation: warp per node, lane handles 2 cols (one half2).
// hout[node] = relu(bias + sum_e dis[col]*dis[node] * hw[col])
// ---------------------------------------------------------------------------
__global__ void __launch_bounds__(256) k_gather(
    const __half2* __restrict__ hw,
    const float* __restrict__ bias,
    float* __restrict__ hout, int n)
{
    int g = blockIdx.x * blockDim.x + threadIdx.x;
    int node = g >> 5;
    int lane = g & 31;
    if (node >= n) return;
    int beg = g_rowptr[node];
    int end = g_rowptr[node + 1];
    float disd = g_dis[node];
    float a0 = 0.f, a1 = 0.f;
    int e = beg;
    for (; e + 1 < end; e += 2) {
        int c0 = __ldg(&g_col[e]);
        int c1 = __ldg(&g_col[e + 1]);
        float v0 = __ldg(&g_dis[c0]) * disd;
        float v1 = __ldg(&g_dis[c1]) * disd;
        float2 f0 = __half22float2(hw[(size_t)c0 * 32 + lane]);
        float2 f1 = __half22float2(hw[(size_t)c1 * 32 + lane]);
        a0 = fmaf(v0, f0.x, a0); a1 = fmaf(v0, f0.y, a1);
        a0 = fmaf(v1, f1.x, a0); a1 = fmaf(v1, f1.y, a1);
    }
    if (e < end) {
        int c0 = __ldg(&g_col[e]);
        float v0 = __ldg(&g_dis[c0]) * disd;
        float2 f0 = __half22float2(hw[(size_t)c0 * 32 + lane]);
        a0 = fmaf(v0, f0.x, a0); a1 = fmaf(v0, f0.y, a1);
    }
    float2 o;
    o.x = fmaxf(a0 + bias[2 * lane], 0.f);
    o.y = fmaxf(a1 + bias[2 * lane + 1], 0.f);
    *(float2*)&hout[(size_t)node * 64 + 2 * lane] = o;
}

// ---------------------------------------------------------------------------
extern "C" void kernel_launch(void* const* d_in, const int* in_sizes, int n_in,
                              void* d_out, int out_size)
{
    const float* x  = (const float*)d_in[0];
    const int*   ei = (const int*)d_in[1];     // int32 edge_index [2, E]
    const float* W0 = (const float*)d_in[2];
    const float* b0 = (const float*)d_in[3];
    const float* W1 = (const float*)d_in[4];
    const float* b1 = (const float*)d_in[5];
    const float* W2 = (const float*)d_in[6];
    const float* b2 = (const float*)d_in[7];
    const float* Wl = (const float*)d_in[8];
    const float* bl = (const float*)d_in[9];
    float* out = (float*)d_out;

    int n = in_sizes[0] / 128;
    int e = in_sizes[1] / 2;
    int nb = (n + 1023) >> 10;

    __half2* hw_ptr = nullptr;
    float* h1_ptr = nullptr;
    float* h2_ptr = nullptr;
    float* h3_ptr = nullptr;
    cudaGetSymbolAddress((void**)&hw_ptr, g_hw);
    cudaGetSymbolAddress((void**)&h1_ptr, g_h1);
    cudaGetSymbolAddress((void**)&h2_ptr, g_h2);
    cudaGetSymbolAddress((void**)&h3_ptr, g_h3);

    // ---- CSR build ----
    k_init_deg<<<(n + 255) / 256, 256>>>(n);
    int cthreads = (e + 3) / 4;
    k_count4<<<(cthreads + 255) / 256, 256>>>(ei, e);
    k_scan_local<<<nb, 1024>>>(n);
    k_scan_bsums<<<1, 128>>>(nb, n);
    k_scan_add<<<nb, 1024>>>(n);
    k_fill<<<(e + n + 255) / 256, 256>>>(ei, e, n);

    int gemm_blocks = (n + TR2 - 1) / TR2;
    int gather_blocks = (n * 32 + 255) / 256;

    // ---- layer 1 ----
    k_gemm2h<<<gemm_blocks, 128>>>(x, 128, W0, hw_ptr, n);
    k_gather<<<gather_blocks, 256>>>(hw_ptr, b0, h1_ptr, n);
    // ---- layer 2 ----
    k_gemm2h<<<gemm_blocks, 128>>>(h1_ptr, 64, W1, hw_ptr, n);
    k_gather<<<gather_blocks, 256>>>(hw_ptr, b1, h2_ptr, n);
    // ---- layer 3 ----
    k_gemm2h<<<gemm_blocks, 128>>>(h2_ptr, 64, W2, hw_ptr, n);
    k_gather<<<gather_blocks, 256>>>(hw_ptr, b2, h3_ptr, n);
    // ---- JK concat + linear ----
    k_gemm_cat2<<<gemm_blocks, 128>>>(x, Wl, bl, out, n);
}

// round 5
// speedup vs baseline: 1.5602x; 1.5602x over previous
#include <cuda_runtime.h>
#include <cuda_fp16.h>

// ---------------------------------------------------------------------------
// GCN_JK_Concat: 3x GCNConv(sym-norm, self-loops) + JK concat + Linear
// N=100000, E=1600000, F_IN=128, H=64, F_OUT=64
// R5: fp16 message features (half gather bytes) + streaming precomputed
// g_val (1 random L2 request per edge, like R3). Scalar count restored.
// Gather unrolled x4.
// ---------------------------------------------------------------------------

#define NMAX   100000
#define EMAX   1600000
#define NNZMAX (EMAX + NMAX)
#define NBSCAN 128

__device__ int     g_deg[NMAX];
__device__ float   g_dis[NMAX];
__device__ int     g_rowptr[NMAX + 1];
__device__ int     g_cursor[NMAX];
__device__ int     g_bsum[NBSCAN];
__device__ int     g_boff[NBSCAN];
__device__ int     g_col[NNZMAX];
__device__ float   g_val[NNZMAX];
__device__ __half2 g_hw[(size_t)NMAX * 32];   // fp16 transformed features
__device__ float   g_h1[(size_t)NMAX * 64];
__device__ float   g_h2[(size_t)NMAX * 64];
__device__ float   g_h3[(size_t)NMAX * 64];

// ---------------------------------------------------------------------------
__global__ void k_init_deg(int n) {
    int i = blockIdx.x * blockDim.x + threadIdx.x;
    if (i < n) g_deg[i] = 1;   // self-loop
}

__global__ void k_count(const int* __restrict__ ei, int e) {
    int i = blockIdx.x * blockDim.x + threadIdx.x;
    if (i < e) {
        int d = ei[(size_t)e + i];   // row 1 = dst
        atomicAdd(&g_deg[d], 1);
    }
}

// ---- 3-pass parallel scan ----
__global__ void __launch_bounds__(1024) k_scan_local(int n) {
    __shared__ int warpsum[32];
    int t = threadIdx.x;
    int lane = t & 31;
    int w = t >> 5;
    int i = blockIdx.x * 1024 + t;
    int v = (i < n) ? g_deg[i] : 0;
    int s = v;
    #pragma unroll
    for (int o = 1; o < 32; o <<= 1) {
        int x = __shfl_up_sync(0xffffffffu, s, o);
        if (lane >= o) s += x;
    }
    if (lane == 31) warpsum[w] = s;
    __syncthreads();
    if (w == 0) {
        int v2 = warpsum[lane];
        #pragma unroll
        for (int o = 1; o < 32; o <<= 1) {
            int x = __shfl_up_sync(0xffffffffu, v2, o);
            if (lane >= o) v2 += x;
        }
        warpsum[lane] = v2;
    }
    __syncthreads();
    int prefix = (w == 0) ? 0 : warpsum[w - 1];
    int incl = prefix + s;
    if (i < n) {
        g_rowptr[i] = incl - v;          // local exclusive
        g_dis[i] = rsqrtf((float)v);
    }
    if (t == 1023) g_bsum[blockIdx.x] = incl;
}

__global__ void __launch_bounds__(128) k_scan_bsums(int nb, int n) {
    int t = threadIdx.x;
    int lane = t & 31;
    int w = t >> 5;
    __shared__ int warpsum[4];
    int v = (t < nb) ? g_bsum[t] : 0;
    int s = v;
    #pragma unroll
    for (int o = 1; o < 32; o <<= 1) {
        int x = __shfl_up_sync(0xffffffffu, s, o);
        if (lane >= o) s += x;
    }
    if (lane == 31) warpsum[w] = s;
    __syncthreads();
    int pre = 0;
    for (int j = 0; j < w; j++) pre += warpsum[j];
    if (t < nb) g_boff[t] = pre + s - v;
    if (t == nb - 1) g_rowptr[n] = pre + s;
}

__global__ void __launch_bounds__(1024) k_scan_add(int n) {
    int i = blockIdx.x * 1024 + threadIdx.x;
    if (i < n) {
        int rp = g_rowptr[i] + g_boff[blockIdx.x];
        g_rowptr[i] = rp;
        g_cursor[i] = rp;
    }
}

__global__ void k_fill(const int* __restrict__ ei, int e, int n) {
    int i = blockIdx.x * blockDim.x + threadIdx.x;
    int s, d;
    if (i < e) {
        s = ei[i];
        d = ei[(size_t)e + i];
    } else if (i < e + n) {
        s = d = i - e;                  // self-loop
    } else {
        return;
    }
    int pos = atomicAdd(&g_cursor[d], 1);
    g_col[pos] = s;
    g_val[pos] = g_dis[s] * g_dis[d];
}

// ---------------------------------------------------------------------------
// GEMM: 128 rows/block, 128 threads, 8x8 register tile, fma.rn.f32x2.
// ---------------------------------------------------------------------------
#define TR2 128
#define TK2 32

#define FMA2(acc, a, b) \
    asm("fma.rn.f32x2 %0, %1, %2, %0;" : "+l"(acc) : "l"(a), "l"(b))

__device__ __forceinline__ unsigned long long bcast2(float a) {
    unsigned long long r;
    asm("mov.b64 %0, {%1, %1};" : "=l"(r) : "f"(a));
    return r;
}

struct GemmSmem {
    float xs[TR2][TK2 + 5];   // stride 37: conflict-free scalar reads
    float ws[TK2][64 + 4];    // stride 68: aligned LDS.128, broadcast
};

__device__ __forceinline__ void gemm_tile_load_W(
    GemmSmem* sm, const float* __restrict__ W, int kk, int t)
{
    #pragma unroll
    for (int s = 0; s < 4; s++) {
        int slot = t + s * 128;
        int k = slot >> 4;
        int c4 = slot & 15;
        *(float4*)&sm->ws[k][c4 * 4] = *(const float4*)&W[(size_t)(kk + k) * 64 + c4 * 4];
    }
}

__device__ __forceinline__ void gemm_tile_load_A(
    GemmSmem* sm, const float* __restrict__ A, int K, int kk,
    int rowBase, int n, int t)
{
    #pragma unroll
    for (int s = 0; s < 8; s++) {
        int slot = t + s * 128;
        int r = slot >> 3;
        int k4 = slot & 7;
        int row = rowBase + r;
        float4 v = make_float4(0.f, 0.f, 0.f, 0.f);
        if (row < n) v = *(const float4*)&A[(size_t)row * K + kk + k4 * 4];
        sm->xs[r][k4 * 4 + 0] = v.x;
        sm->xs[r][k4 * 4 + 1] = v.y;
        sm->xs[r][k4 * 4 + 2] = v.z;
        sm->xs[r][k4 * 4 + 3] = v.w;
    }
}

__device__ __forceinline__ void gemm_tile_compute(
    GemmSmem* sm, int tx, int ty, unsigned long long acc[8][4])
{
    #pragma unroll
    for (int k = 0; k < TK2; k++) {
        ulonglong2 wA = *(const ulonglong2*)&sm->ws[k][8 * tx];
        ulonglong2 wB = *(const ulonglong2*)&sm->ws[k][8 * tx + 4];
        #pragma unroll
        for (int i = 0; i < 8; i++) {
            unsigned long long aa = bcast2(sm->xs[8 * ty + i][k]);
            FMA2(acc[i][0], aa, wA.x);
            FMA2(acc[i][1], aa, wA.y);
            FMA2(acc[i][2], aa, wB.x);
            FMA2(acc[i][3], aa, wB.y);
        }
    }
}

// transform GEMM writing fp16 messages
__global__ void __launch_bounds__(128) k_gemm2h(
    const float* __restrict__ A, int K,
    const float* __restrict__ W,
    __half2* __restrict__ out, int n)
{
    __shared__ GemmSmem sm;
    int t = threadIdx.x;
    int tx = t & 7, ty = t >> 3;
    int rowBase = blockIdx.x * TR2;
    unsigned long long acc[8][4] = {};

    for (int kk = 0; kk < K; kk += TK2) {
        gemm_tile_load_A(&sm, A, K, kk, rowBase, n, t);
        gemm_tile_load_W(&sm, W, kk, t);
        __syncthreads();
        gemm_tile_compute(&sm, tx, ty, acc);
        __syncthreads();
    }
    #pragma unroll
    for (int i = 0; i < 8; i++) {
        int row = rowBase + 8 * ty + i;
        if (row < n) {
            union { uint4 u; __half2 h[4]; } p;
            p.h[0] = __float22half2_rn(*(float2*)&acc[i][0]);
            p.h[1] = __float22half2_rn(*(float2*)&acc[i][1]);
            p.h[2] = __float22half2_rn(*(float2*)&acc[i][2]);
            p.h[3] = __float22half2_rn(*(float2*)&acc[i][3]);
            *(uint4*)&out[(size_t)row * 32 + 4 * tx] = p.u;
        }
    }
}

// Final GEMM on virtual concat [x | h1 | h2 | h3] (K=320) with bias, fp32 out.
__global__ void __launch_bounds__(128) k_gemm_cat2(
    const float* __restrict__ x,
    const float* __restrict__ Wl,
    const float* __restrict__ bl,
    float* __restrict__ out, int n)
{
    __shared__ GemmSmem sm;
    int t = threadIdx.x;
    int tx = t & 7, ty = t >> 3;
    int rowBase = blockIdx.x * TR2;
    unsigned long long acc[8][4] = {};

    for (int kk = 0; kk < 320; kk += TK2) {
        const float* src;
        int stride, koff;
        if (kk < 128)      { src = x;    stride = 128; koff = kk; }
        else if (kk < 192) { src = g_h1; stride = 64;  koff = kk - 128; }
        else if (kk < 256) { src = g_h2; stride = 64;  koff = kk - 192; }
        else               { src = g_h3; stride = 64;  koff = kk - 256; }

        gemm_tile_load_A(&sm, src, stride, koff, rowBase, n, t);
        gemm_tile_load_W(&sm, Wl, kk, t);
        __syncthreads();
        gemm_tile_compute(&sm, tx, ty, acc);
        __syncthreads();
    }
    float4 bv0 = *(const float4*)&bl[8 * tx];
    float4 bv1 = *(const float4*)&bl[8 * tx + 4];
    #pragma unroll
    for (int i = 0; i < 8; i++) {
        int row = rowBase + 8 * ty + i;
        if (row < n) {
            float2 f0 = *(float2*)&acc[i][0];
            float2 f1 = *(float2*)&acc[i][1];
            float2 f2 = *(float2*)&acc[i][2];
            float2 f3 = *(float2*)&acc[i][3];
            *(float4*)&out[(size_t)row * 64 + 8 * tx] =
                make_float4(f0.x + bv0.x, f0.y + bv0.y, f1.x + bv0.z, f1.y + bv0.w);
            *(float4*)&out[(size_t)row * 64 + 8 * tx + 4] =
                make_float4(f2.x + bv1.x, f2.y + bv1.y, f3.x + bv1.z, f3.y + bv1.w);
        }
    }
}

// ---------------------------------------------------------------------------
// Aggregation: warp per node, lane handles 2 cols (one half2), unroll x4.
// hout[node] = relu(bias + sum_e val[e] * hw[col[e]])
// ---------------------------------------------------------------------------
__global__ void __launch_bounds__(256) k_gather(
    const __half2* __restrict__ hw,
    const float* __restrict__ bias,
    float* __restrict__ hout, int n)
{
    int g = blockIdx.x * blockDim.x + threadIdx.x;
    int node = g >> 5;
    int lane = g & 31;
    if (node >= n) return;
    int beg = g_rowptr[node];
    int end = g_rowptr[node + 1];
    float a0 = 0.f, a1 = 0.f;
    int e = beg;
    for (; e + 3 < end; e += 4) {
        int c0 = __ldg(&g_col[e]);
        int c1 = __ldg(&g_col[e + 1]);
        int c2 = __ldg(&g_col[e + 2]);
        int c3 = __ldg(&g_col[e + 3]);
        float v0 = __ldg(&g_val[e]);
        float v1 = __ldg(&g_val[e + 1]);
        float v2 = __ldg(&g_val[e + 2]);
        float v3 = __ldg(&g_val[e + 3]);
        float2 f0 = __half22float2(hw[(size_t)c0 * 32 + lane]);
        float2 f1 = __half22float2(hw[(size_t)c1 * 32 + lane]);
        float2 f2 = __half22float2(hw[(size_t)c2 * 32 + lane]);
        float2 f3 = __half22float2(hw[(size_t)c3 * 32 + lane]);
        a0 = fmaf(v0, f0.x, a0); a1 = fmaf(v0, f0.y, a1);
        a0 = fmaf(v1, f1.x, a0); a1 = fmaf(v1, f1.y, a1);
        a0 = fmaf(v2, f2.x, a0); a1 = fmaf(v2, f2.y, a1);
        a0 = fmaf(v3, f3.x, a0); a1 = fmaf(v3, f3.y, a1);
    }
    for (; e < end; e++) {
        int c0 = __ldg(&g_col[e]);
        float v0 = __ldg(&g_val[e]);
        float2 f0 = __half22float2(hw[(size_t)c0 * 32 + lane]);
        a0 = fmaf(v0, f0.x, a0); a1 = fmaf(v0, f0.y, a1);
    }
    float2 o;
    o.x = fmaxf(a0 + bias[2 * lane], 0.f);
    o.y = fmaxf(a1 + bias[2 * lane + 1], 0.f);
    *(float2*)&hout[(size_t)node * 64 + 2 * lane] = o;
}

// ---------------------------------------------------------------------------
extern "C" void kernel_launch(void* const* d_in, const int* in_sizes, int n_in,
                              void* d_out, int out_size)
{
    const float* x  = (const float*)d_in[0];
    const int*   ei = (const int*)d_in[1];     // int32 edge_index [2, E]
    const float* W0 = (const float*)d_in[2];
    const float* b0 = (const float*)d_in[3];
    const float* W1 = (const float*)d_in[4];
    const float* b1 = (const float*)d_in[5];
    const float* W2 = (const float*)d_in[6];
    const float* b2 = (const float*)d_in[7];
    const float* Wl = (const float*)d_in[8];
    const float* bl = (const float*)d_in[9];
    float* out = (float*)d_out;

    int n = in_sizes[0] / 128;
    int e = in_sizes[1] / 2;
    int nb = (n + 1023) >> 10;

    __half2* hw_ptr = nullptr;
    float* h1_ptr = nullptr;
    float* h2_ptr = nullptr;
    float* h3_ptr = nullptr;
    cudaGetSymbolAddress((void**)&hw_ptr, g_hw);
    cudaGetSymbolAddress((void**)&h1_ptr, g_h1);
    cudaGetSymbolAddress((void**)&h2_ptr, g_h2);
    cudaGetSymbolAddress((void**)&h3_ptr, g_h3);

    // ---- CSR build ----
    k_init_deg<<<(n + 255) / 256, 256>>>(n);
    k_count<<<(e + 255) / 256, 256>>>(ei, e);
    k_scan_local<<<nb, 1024>>>(n);
    k_scan_bsums<<<1, 128>>>(nb, n);
    k_scan_add<<<nb, 1024>>>(n);
    k_fill<<<(e + n + 255) / 256, 256>>>(ei, e, n);

    int gemm_blocks = (n + TR2 - 1) / TR2;
    int gather_blocks = (n * 32 + 255) / 256;

    // ---- layer 1 ----
    k_gemm2h<<<gemm_blocks, 128>>>(x, 128, W0, hw_ptr, n);
    k_gather<<<gather_blocks, 256>>>(hw_ptr, b0, h1_ptr, n);
    // ---- layer 2 ----
    k_gemm2h<<<gemm_blocks, 128>>>(h1_ptr, 64, W1, hw_ptr, n);
    k_gather<<<gather_blocks, 256>>>(hw_ptr, b1, h2_ptr, n);
    // ---- layer 3 ----
    k_gemm2h<<<gemm_blocks, 128>>>(h2_ptr, 64, W2, hw_ptr, n);
    k_gather<<<gather_blocks, 256>>>(hw_ptr, b2, h3_ptr, n);
    // ---- JK concat + linear ----
    k_gemm_cat2<<<gemm_blocks, 128>>>(x, Wl, bl, out, n);
}

// round 7
// speedup vs baseline: 1.8086x; 1.1592x over previous
#include <cuda_runtime.h>
#include <cuda_fp16.h>
#include <cstdint>

// ---------------------------------------------------------------------------
// GCN_JK_Concat: 3x GCNConv(sym-norm, self-loops) + JK concat + Linear
// N=100000, E=1600000, F_IN=128, H=64, F_OUT=64
// R7: GEMMs on mma.sync m16n8k16 (HMMA, base PTX -- tcgen05 is 'a'-gated and
// the harness targets sm_103 without 'a'). fp16 operands, fp32 accum.
// Packed (col,val) CSR entries; fp16 h1..h3.
// ---------------------------------------------------------------------------

#define NMAX   100000
#define EMAX   1600000
#define NNZMAX (EMAX + NMAX)
#define NBSCAN 128

__device__ int     g_deg[NMAX];
__device__ float   g_dis[NMAX];
__device__ int     g_rowptr[NMAX + 1];
__device__ int     g_cursor[NMAX];
__device__ int     g_bsum[NBSCAN];
__device__ int     g_boff[NBSCAN];
__device__ int2    g_cv[NNZMAX];              // packed (col, val-bits)
__device__ __half2 g_hw[(size_t)NMAX * 32];   // fp16 transformed features
__device__ __half2 g_h1[(size_t)NMAX * 32];
__device__ __half2 g_h2[(size_t)NMAX * 32];
__device__ __half2 g_h3[(size_t)NMAX * 32];

// ===========================================================================
// CSR build
// ===========================================================================
__global__ void k_init_deg(int n) {
    int i = blockIdx.x * blockDim.x + threadIdx.x;
    if (i < n) g_deg[i] = 1;   // self-loop
}

__global__ void k_count(const int* __restrict__ ei, int e) {
    int i = blockIdx.x * blockDim.x + threadIdx.x;
    if (i < e) atomicAdd(&g_deg[ei[(size_t)e + i]], 1);
}

__global__ void __launch_bounds__(1024) k_scan_local(int n) {
    __shared__ int warpsum[32];
    int t = threadIdx.x;
    int lane = t & 31;
    int w = t >> 5;
    int i = blockIdx.x * 1024 + t;
    int v = (i < n) ? g_deg[i] : 0;
    int s = v;
    #pragma unroll
    for (int o = 1; o < 32; o <<= 1) {
        int x = __shfl_up_sync(0xffffffffu, s, o);
        if (lane >= o) s += x;
    }
    if (lane == 31) warpsum[w] = s;
    __syncthreads();
    if (w == 0) {
        int v2 = warpsum[lane];
        #pragma unroll
        for (int o = 1; o < 32; o <<= 1) {
            int x = __shfl_up_sync(0xffffffffu, v2, o);
            if (lane >= o) v2 += x;
        }
        warpsum[lane] = v2;
    }
    __syncthreads();
    int prefix = (w == 0) ? 0 : warpsum[w - 1];
    int incl = prefix + s;
    if (i < n) {
        g_rowptr[i] = incl - v;
        g_dis[i] = rsqrtf((float)v);
    }
    if (t == 1023) g_bsum[blockIdx.x] = incl;
}

__global__ void __launch_bounds__(128) k_scan_bsums(int nb, int n) {
    int t = threadIdx.x;
    int lane = t & 31;
    int w = t >> 5;
    __shared__ int warpsum[4];
    int v = (t < nb) ? g_bsum[t] : 0;
    int s = v;
    #pragma unroll
    for (int o = 1; o < 32; o <<= 1) {
        int x = __shfl_up_sync(0xffffffffu, s, o);
        if (lane >= o) s += x;
    }
    if (lane == 31) warpsum[w] = s;
    __syncthreads();
    int pre = 0;
    for (int j = 0; j < w; j++) pre += warpsum[j];
    if (t < nb) g_boff[t] = pre + s - v;
    if (t == nb - 1) g_rowptr[n] = pre + s;
}

__global__ void __launch_bounds__(1024) k_scan_add(int n) {
    int i = blockIdx.x * 1024 + threadIdx.x;
    if (i < n) {
        int rp = g_rowptr[i] + g_boff[blockIdx.x];
        g_rowptr[i] = rp;
        g_cursor[i] = rp;
    }
}

__global__ void k_fill(const int* __restrict__ ei, int e, int n) {
    int i = blockIdx.x * blockDim.x + threadIdx.x;
    int s, d;
    if (i < e) {
        s = ei[i];
        d = ei[(size_t)e + i];
    } else if (i < e + n) {
        s = d = i - e;                  // self-loop
    } else {
        return;
    }
    int pos = atomicAdd(&g_cursor[d], 1);
    g_cv[pos] = make_int2(s, __float_as_int(g_dis[s] * g_dis[d]));
}

// ===========================================================================
// HMMA GEMM: out[n,64] = A[n,K] @ W[K,64]
// 128 rows/block, 128 threads (4 warps); warp = 32 rows x 64 cols.
// mma.sync.m16n8k16 f16*f16 -> f32.
// ===========================================================================
#define PADH 72   // half-element row pitch (144 B): ldmatrix conflict-free

__device__ __forceinline__ uint32_t smem_u32(const void* p) {
    return (uint32_t)__cvta_generic_to_shared(p);
}

#define LDSM_X4(r0, r1, r2, r3, addr) \
    asm volatile("ldmatrix.sync.aligned.m8n8.x4.shared.b16 {%0,%1,%2,%3}, [%4];" \
        : "=r"(r0), "=r"(r1), "=r"(r2), "=r"(r3) : "r"(addr))

#define LDSM_X4_T(r0, r1, r2, r3, addr) \
    asm volatile("ldmatrix.sync.aligned.m8n8.x4.trans.shared.b16 {%0,%1,%2,%3}, [%4];" \
        : "=r"(r0), "=r"(r1), "=r"(r2), "=r"(r3) : "r"(addr))

#define MMA16816(d, a, b0, b1) \
    asm volatile("mma.sync.aligned.m16n8k16.row.col.f32.f16.f16.f32 " \
        "{%0,%1,%2,%3}, {%4,%5,%6,%7}, {%8,%9}, {%0,%1,%2,%3};" \
        : "+f"((d)[0]), "+f"((d)[1]), "+f"((d)[2]), "+f"((d)[3]) \
        : "r"((a)[0]), "r"((a)[1]), "r"((a)[2]), "r"((a)[3]), "r"(b0), "r"(b1))

struct HSmem {
    __half sA[128][PADH];   // 128 rows x 64 k
    __half sB[64][PADH];    // 64 k x 64 n
};

__device__ __forceinline__ void load_A32(
    HSmem* sm, const float* __restrict__ A, int K, int kk,
    int rowBase, int n, int t)
{
    for (int idx = t; idx < 4096; idx += 128) {
        int row = idx >> 5, kp = idx & 31;
        int gr = rowBase + row;
        float2 f = make_float2(0.f, 0.f);
        if (gr < n) f = *(const float2*)&A[(size_t)gr * K + kk + 2 * kp];
        *(__half2*)&sm->sA[row][2 * kp] = __float22half2_rn(f);
    }
}

__device__ __forceinline__ void load_A16(
    HSmem* sm, const __half2* __restrict__ H, int rowBase, int n, int t)
{
    for (int idx = t; idx < 1024; idx += 128) {   // 128 rows x 8 uint4
        int row = idx >> 3, q = idx & 7;
        int gr = rowBase + row;
        uint4 v = make_uint4(0u, 0u, 0u, 0u);
        if (gr < n) v = *(const uint4*)&H[(size_t)gr * 32 + 4 * q];
        *(uint4*)&sm->sA[row][8 * q] = v;          // 144B pitch -> 16B aligned
    }
}

__device__ __forceinline__ void load_B(
    HSmem* sm, const float* __restrict__ W, int kk, int t)
{
    for (int idx = t; idx < 2048; idx += 128) {
        int k = idx >> 5, np = idx & 31;
        float2 f = *(const float2*)&W[(size_t)(kk + k) * 64 + 2 * np];
        *(__half2*)&sm->sB[k][2 * np] = __float22half2_rn(f);
    }
}

// acc[m][j][4]: m = 16-row sub-tile (0,1), j = 8-col sub-tile (0..7)
__device__ __forceinline__ void hmma_tile(
    HSmem* sm, int warp, int lane, float acc[2][8][4])
{
    #pragma unroll
    for (int kc = 0; kc < 4; kc++) {
        int k0 = kc * 16;
        uint32_t a[2][4];
        #pragma unroll
        for (int m = 0; m < 2; m++) {
            uint32_t addr = smem_u32(
                &sm->sA[warp * 32 + m * 16 + (lane & 15)][k0 + (lane >> 4) * 8]);
            LDSM_X4(a[m][0], a[m][1], a[m][2], a[m][3], addr);
        }
        #pragma unroll
        for (int jp = 0; jp < 4; jp++) {
            uint32_t b[4];
            uint32_t addr = smem_u32(
                &sm->sB[k0 + (lane & 15)][jp * 16 + (lane >> 4) * 8]);
            LDSM_X4_T(b[0], b[1], b[2], b[3], addr);
            #pragma unroll
            for (int m = 0; m < 2; m++) {
                MMA16816(acc[m][2 * jp],     a[m], b[0], b[1]);
                MMA16816(acc[m][2 * jp + 1], a[m], b[2], b[3]);
            }
        }
    }
}

// Transform GEMM: out fp16 [n,64]. A fp32 (layer 1) or fp16 (layers 2,3).
__global__ void __launch_bounds__(128) k_hmma_xform(
    const float* __restrict__ A32,
    const __half2* __restrict__ A16,
    int K,
    const float* __restrict__ W,
    __half2* __restrict__ out, int n)
{
    __shared__ HSmem sm;
    int t = threadIdx.x;
    int lane = t & 31, warp = t >> 5;
    int rowBase = blockIdx.x * 128;
    float acc[2][8][4] = {};

    int nt = K >> 6;
    for (int i = 0; i < nt; i++) {
        if (A32) load_A32(&sm, A32, K, i * 64, rowBase, n, t);
        else     load_A16(&sm, A16 + (size_t)(i * 32), rowBase, n, t);
        load_B(&sm, W, i * 64, t);
        __syncthreads();
        hmma_tile(&sm, warp, lane, acc);
        __syncthreads();
    }

    int rw = rowBase + warp * 32;
    #pragma unroll
    for (int m = 0; m < 2; m++) {
        int r0 = rw + m * 16 + (lane >> 2);
        int r1 = r0 + 8;
        #pragma unroll
        for (int j = 0; j < 8; j++) {
            int col = 8 * j + 2 * (lane & 3);
            if (r0 < n)
                out[(size_t)r0 * 32 + (col >> 1)] =
                    __floats2half2_rn(acc[m][j][0], acc[m][j][1]);
            if (r1 < n)
                out[(size_t)r1 * 32 + (col >> 1)] =
                    __floats2half2_rn(acc[m][j][2], acc[m][j][3]);
        }
    }
}

// Final concat GEMM: out fp32 [n,64] = [x|h1|h2|h3] @ Wl + bl  (K=320)
__global__ void __launch_bounds__(128) k_hmma_cat(
    const float* __restrict__ x,
    const float* __restrict__ Wl,
    const float* __restrict__ bl,
    float* __restrict__ out, int n)
{
    __shared__ HSmem sm;
    int t = threadIdx.x;
    int lane = t & 31, warp = t >> 5;
    int rowBase = blockIdx.x * 128;
    float acc[2][8][4] = {};

    for (int i = 0; i < 5; i++) {
        if (i < 2)       load_A32(&sm, x, 128, i * 64, rowBase, n, t);
        else if (i == 2) load_A16(&sm, g_h1, rowBase, n, t);
        else if (i == 3) load_A16(&sm, g_h2, rowBase, n, t);
        else             load_A16(&sm, g_h3, rowBase, n, t);
        load_B(&sm, Wl, i * 64, t);
        __syncthreads();
        hmma_tile(&sm, warp, lane, acc);
        __syncthreads();
    }

    int rw = rowBase + warp * 32;
    #pragma unroll
    for (int m = 0; m < 2; m++) {
        int r0 = rw + m * 16 + (lane >> 2);
        int r1 = r0 + 8;
        #pragma unroll
        for (int j = 0; j < 8; j++) {
            int col = 8 * j + 2 * (lane & 3);
            float b0 = bl[col], b1 = bl[col + 1];
            if (r0 < n)
                *(float2*)&out[(size_t)r0 * 64 + col] =
                    make_float2(acc[m][j][0] + b0, acc[m][j][1] + b1);
            if (r1 < n)
                *(float2*)&out[(size_t)r1 * 64 + col] =
                    make_float2(acc[m][j][2] + b0, acc[m][j][3] + b1);
        }
    }
}

// ===========================================================================
// Aggregation: warp per node, lane handles one half2 (2 cols), unroll x4.
// hout[node] = fp16( relu(bias + sum_e val[e] * hw[col[e]]) )
// ===========================================================================
__global__ void __launch_bounds__(256) k_gather(
    const __half2* __restrict__ hw,
    const float* __restrict__ bias,
    __half2* __restrict__ hout, int n)
{
    int g = blockIdx.x * blockDim.x + threadIdx.x;
    int node = g >> 5;
    int lane = g & 31;
    if (node >= n) return;
    int beg = g_rowptr[node];
    int end = g_rowptr[node + 1];
    float a0 = 0.f, a1 = 0.f;
    int e = beg;
    for (; e + 3 < end; e += 4) {
        int2 cv0 = __ldg(&g_cv[e]);
        int2 cv1 = __ldg(&g_cv[e + 1]);
        int2 cv2 = __ldg(&g_cv[e + 2]);
        int2 cv3 = __ldg(&g_cv[e + 3]);
        float2 f0 = __half22float2(hw[(size_t)cv0.x * 32 + lane]);
        float2 f1 = __half22float2(hw[(size_t)cv1.x * 32 + lane]);
        float2 f2 = __half22float2(hw[(size_t)cv2.x * 32 + lane]);
        float2 f3 = __half22float2(hw[(size_t)cv3.x * 32 + lane]);
        float v0 = __int_as_float(cv0.y);
        float v1 = __int_as_float(cv1.y);
        float v2 = __int_as_float(cv2.y);
        float v3 = __int_as_float(cv3.y);
        a0 = fmaf(v0, f0.x, a0); a1 = fmaf(v0, f0.y, a1);
        a0 = fmaf(v1, f1.x, a0); a1 = fmaf(v1, f1.y, a1);
        a0 = fmaf(v2, f2.x, a0); a1 = fmaf(v2, f2.y, a1);
        a0 = fmaf(v3, f3.x, a0); a1 = fmaf(v3, f3.y, a1);
    }
    for (; e < end; e++) {
        int2 cv = __ldg(&g_cv[e]);
        float2 f = __half22float2(hw[(size_t)cv.x * 32 + lane]);
        float v = __int_as_float(cv.y);
        a0 = fmaf(v, f.x, a0); a1 = fmaf(v, f.y, a1);
    }
    float b0 = bias[2 * lane], b1 = bias[2 * lane + 1];
    hout[(size_t)node * 32 + lane] =
        __floats2half2_rn(fmaxf(a0 + b0, 0.f), fmaxf(a1 + b1, 0.f));
}

// ---------------------------------------------------------------------------
extern "C" void kernel_launch(void* const* d_in, const int* in_sizes, int n_in,
                              void* d_out, int out_size)
{
    const float* x  = (const float*)d_in[0];
    const int*   ei = (const int*)d_in[1];     // int32 edge_index [2, E]
    const float* W0 = (const float*)d_in[2];
    const float* b0 = (const float*)d_in[3];
    const float* W1 = (const float*)d_in[4];
    const float* b1 = (const float*)d_in[5];
    const float* W2 = (const float*)d_in[6];
    const float* b2 = (const float*)d_in[7];
    const float* Wl = (const float*)d_in[8];
    const float* bl = (const float*)d_in[9];
    float* out = (float*)d_out;

    int n = in_sizes[0] / 128;
    int e = in_sizes[1] / 2;
    int nb = (n + 1023) >> 10;

    __half2 *hw_ptr = nullptr, *h1_ptr = nullptr, *h2_ptr = nullptr, *h3_ptr = nullptr;
    cudaGetSymbolAddress((void**)&hw_ptr, g_hw);
    cudaGetSymbolAddress((void**)&h1_ptr, g_h1);
    cudaGetSymbolAddress((void**)&h2_ptr, g_h2);
    cudaGetSymbolAddress((void**)&h3_ptr, g_h3);

    // ---- CSR build ----
    k_init_deg<<<(n + 255) / 256, 256>>>(n);
    k_count<<<(e + 255) / 256, 256>>>(ei, e);
    k_scan_local<<<nb, 1024>>>(n);
    k_scan_bsums<<<1, 128>>>(nb, n);
    k_scan_add<<<nb, 1024>>>(n);
    k_fill<<<(e + n + 255) / 256, 256>>>(ei, e, n);

    int mma_blocks = (n + 127) / 128;
    int gather_blocks = (n * 32 + 255) / 256;

    // ---- layer 1 ----
    k_hmma_xform<<<mma_blocks, 128>>>(x, nullptr, 128, W0, hw_ptr, n);
    k_gather<<<gather_blocks, 256>>>(hw_ptr, b0, h1_ptr, n);
    // ---- layer 2 ----
    k_hmma_xform<<<mma_blocks, 128>>>(nullptr, h1_ptr, 64, W1, hw_ptr, n);
    k_gather<<<gather_blocks, 256>>>(hw_ptr, b1, h2_ptr, n);
    // ---- layer 3 ----
    k_hmma_xform<<<mma_blocks, 128>>>(nullptr, h2_ptr, 64, W2, hw_ptr, n);
    k_gather<<<gather_blocks, 256>>>(hw_ptr, b2, h3_ptr, n);
    // ---- JK concat + linear ----
    k_hmma_cat<<<mma_blocks, 128>>>(x, Wl, bl, out, n);
}

// round 8
// speedup vs baseline: 1.8565x; 1.0265x over previous
#include <cuda_runtime.h>
#include <cuda_fp16.h>
#include <cstdint>

// ---------------------------------------------------------------------------
// GCN_JK_Concat: 3x GCNConv(sym-norm, self-loops) + JK concat + Linear
// N=100000, E=1600000, F_IN=128, H=64, F_OUT=64
// R8: gather unrolled x8 (hide L2 latency: cv loads batched ahead of feature
// loads); k_init_deg folded into scan (deg array self-resetting);
// k_count vectorized x2. GEMMs on HMMA mma.sync (R7).
// ---------------------------------------------------------------------------

#define NMAX   100000
#define EMAX   1600000
#define NNZMAX (EMAX + NMAX)
#define NBSCAN 128

__device__ int     g_deg[NMAX];               // starts 0; reset by scan
__device__ float   g_dis[NMAX];
__device__ int     g_rowptr[NMAX + 1];
__device__ int     g_cursor[NMAX];
__device__ int     g_bsum[NBSCAN];
__device__ int     g_boff[NBSCAN];
__device__ int2    g_cv[NNZMAX];              // packed (col, val-bits)
__device__ __half2 g_hw[(size_t)NMAX * 32];   // fp16 transformed features
__device__ __half2 g_h1[(size_t)NMAX * 32];
__device__ __half2 g_h2[(size_t)NMAX * 32];
__device__ __half2 g_h3[(size_t)NMAX * 32];

// ===========================================================================
// CSR build
// ===========================================================================
// 2 edges per thread; deg starts at 0 (self-loop added in scan).
__global__ void k_count2(const int* __restrict__ ei, int e) {
    int i = blockIdx.x * blockDim.x + threadIdx.x;
    int base = 2 * i;
    if (base + 1 < e) {
        int2 d = *(const int2*)&ei[(size_t)e + base];
        atomicAdd(&g_deg[d.x], 1);
        atomicAdd(&g_deg[d.y], 1);
    } else if (base < e) {
        atomicAdd(&g_deg[ei[(size_t)e + base]], 1);
    }
}

__global__ void __launch_bounds__(1024) k_scan_local(int n) {
    __shared__ int warpsum[32];
    int t = threadIdx.x;
    int lane = t & 31;
    int w = t >> 5;
    int i = blockIdx.x * 1024 + t;
    int v = 0;
    if (i < n) {
        v = g_deg[i] + 1;        // +1 = self-loop
        g_deg[i] = 0;            // reset for next graph replay
    }
    int s = v;
    #pragma unroll
    for (int o = 1; o < 32; o <<= 1) {
        int x = __shfl_up_sync(0xffffffffu, s, o);
        if (lane >= o) s += x;
    }
    if (lane == 31) warpsum[w] = s;
    __syncthreads();
    if (w == 0) {
        int v2 = warpsum[lane];
        #pragma unroll
        for (int o = 1; o < 32; o <<= 1) {
            int x = __shfl_up_sync(0xffffffffu, v2, o);
            if (lane >= o) v2 += x;
        }
        warpsum[lane] = v2;
    }
    __syncthreads();
    int prefix = (w == 0) ? 0 : warpsum[w - 1];
    int incl = prefix + s;
    if (i < n) {
        g_rowptr[i] = incl - v;
        g_dis[i] = rsqrtf((float)v);
    }
    if (t == 1023) g_bsum[blockIdx.x] = incl;
}

__global__ void __launch_bounds__(128) k_scan_bsums(int nb, int n) {
    int t = threadIdx.x;
    int lane = t & 31;
    int w = t >> 5;
    __shared__ int warpsum[4];
    int v = (t < nb) ? g_bsum[t] : 0;
    int s = v;
    #pragma unroll
    for (int o = 1; o < 32; o <<= 1) {
        int x = __shfl_up_sync(0xffffffffu, s, o);
        if (lane >= o) s += x;
    }
    if (lane == 31) warpsum[w] = s;
    __syncthreads();
    int pre = 0;
    for (int j = 0; j < w; j++) pre += warpsum[j];
    if (t < nb) g_boff[t] = pre + s - v;
    if (t == nb - 1) g_rowptr[n] = pre + s;
}

__global__ void __launch_bounds__(1024) k_scan_add(int n) {
    int i = blockIdx.x * 1024 + threadIdx.x;
    if (i < n) {
        int rp = g_rowptr[i] + g_boff[blockIdx.x];
        g_rowptr[i] = rp;
        g_cursor[i] = rp;
    }
}

__global__ void k_fill(const int* __restrict__ ei, int e, int n) {
    int i = blockIdx.x * blockDim.x + threadIdx.x;
    int s, d;
    if (i < e) {
        s = ei[i];
        d = ei[(size_t)e + i];
    } else if (i < e + n) {
        s = d = i - e;                  // self-loop
    } else {
        return;
    }
    int pos = atomicAdd(&g_cursor[d], 1);
    g_cv[pos] = make_int2(s, __float_as_int(g_dis[s] * g_dis[d]));
}

// ===========================================================================
// HMMA GEMM: out[n,64] = A[n,K] @ W[K,64]
// 128 rows/block, 128 threads (4 warps); warp = 32 rows x 64 cols.
// ===========================================================================
#define PADH 72   // half-element row pitch (144 B): ldmatrix conflict-free

__device__ __forceinline__ uint32_t smem_u32(const void* p) {
    return (uint32_t)__cvta_generic_to_shared(p);
}

#define LDSM_X4(r0, r1, r2, r3, addr) \
    asm volatile("ldmatrix.sync.aligned.m8n8.x4.shared.b16 {%0,%1,%2,%3}, [%4];" \
        : "=r"(r0), "=r"(r1), "=r"(r2), "=r"(r3) : "r"(addr))

#define LDSM_X4_T(r0, r1, r2, r3, addr) \
    asm volatile("ldmatrix.sync.aligned.m8n8.x4.trans.shared.b16 {%0,%1,%2,%3}, [%4];" \
        : "=r"(r0), "=r"(r1), "=r"(r2), "=r"(r3) : "r"(addr))

#define MMA16816(d, a, b0, b1) \
    asm volatile("mma.sync.aligned.m16n8k16.row.col.f32.f16.f16.f32 " \
        "{%0,%1,%2,%3}, {%4,%5,%6,%7}, {%8,%9}, {%0,%1,%2,%3};" \
        : "+f"((d)[0]), "+f"((d)[1]), "+f"((d)[2]), "+f"((d)[3]) \
        : "r"((a)[0]), "r"((a)[1]), "r"((a)[2]), "r"((a)[3]), "r"(b0), "r"(b1))

struct HSmem {
    __half sA[128][PADH];   // 128 rows x 64 k
    __half sB[64][PADH];    // 64 k x 64 n
};

__device__ __forceinline__ void load_A32(
    HSmem* sm, const float* __restrict__ A, int K, int kk,
    int rowBase, int n, int t)
{
    for (int idx = t; idx < 4096; idx += 128) {
        int row = idx >> 5, kp = idx & 31;
        int gr = rowBase + row;
        float2 f = make_float2(0.f, 0.f);
        if (gr < n) f = *(const float2*)&A[(size_t)gr * K + kk + 2 * kp];
        *(__half2*)&sm->sA[row][2 * kp] = __float22half2_rn(f);
    }
}

__device__ __forceinline__ void load_A16(
    HSmem* sm, const __half2* __restrict__ H, int rowBase, int n, int t)
{
    for (int idx = t; idx < 1024; idx += 128) {   // 128 rows x 8 uint4
        int row = idx >> 3, q = idx & 7;
        int gr = rowBase + row;
        uint4 v = make_uint4(0u, 0u, 0u, 0u);
        if (gr < n) v = *(const uint4*)&H[(size_t)gr * 32 + 4 * q];
        *(uint4*)&sm->sA[row][8 * q] = v;
    }
}

__device__ __forceinline__ void load_B(
    HSmem* sm, const float* __restrict__ W, int kk, int t)
{
    for (int idx = t; idx < 2048; idx += 128) {
        int k = idx >> 5, np = idx & 31;
        float2 f = *(const float2*)&W[(size_t)(kk + k) * 64 + 2 * np];
        *(__half2*)&sm->sB[k][2 * np] = __float22half2_rn(f);
    }
}

__device__ __forceinline__ void hmma_tile(
    HSmem* sm, int warp, int lane, float acc[2][8][4])
{
    #pragma unroll
    for (int kc = 0; kc < 4; kc++) {
        int k0 = kc * 16;
        uint32_t a[2][4];
        #pragma unroll
        for (int m = 0; m < 2; m++) {
            uint32_t addr = smem_u32(
                &sm->sA[warp * 32 + m * 16 + (lane & 15)][k0 + (lane >> 4) * 8]);
            LDSM_X4(a[m][0], a[m][1], a[m][2], a[m][3], addr);
        }
        #pragma unroll
        for (int jp = 0; jp < 4; jp++) {
            uint32_t b[4];
            uint32_t addr = smem_u32(
                &sm->sB[k0 + (lane & 15)][jp * 16 + (lane >> 4) * 8]);
            LDSM_X4_T(b[0], b[1], b[2], b[3], addr);
            #pragma unroll
            for (int m = 0; m < 2; m++) {
                MMA16816(acc[m][2 * jp],     a[m], b[0], b[1]);
                MMA16816(acc[m][2 * jp + 1], a[m], b[2], b[3]);
            }
        }
    }
}

__global__ void __launch_bounds__(128) k_hmma_xform(
    const float* __restrict__ A32,
    const __half2* __restrict__ A16,
    int K,
    const float* __restrict__ W,
    __half2* __restrict__ out, int n)
{
    __shared__ HSmem sm;
    int t = threadIdx.x;
    int lane = t & 31, warp = t >> 5;
    int rowBase = blockIdx.x * 128;
    float acc[2][8][4] = {};

    int nt = K >> 6;
    for (int i = 0; i < nt; i++) {
        if (A32) load_A32(&sm, A32, K, i * 64, rowBase, n, t);
        else     load_A16(&sm, A16 + (size_t)(i * 32), rowBase, n, t);
        load_B(&sm, W, i * 64, t);
        __syncthreads();
        hmma_tile(&sm, warp, lane, acc);
        __syncthreads();
    }

    int rw = rowBase + warp * 32;
    #pragma unroll
    for (int m = 0; m < 2; m++) {
        int r0 = rw + m * 16 + (lane >> 2);
        int r1 = r0 + 8;
        #pragma unroll
        for (int j = 0; j < 8; j++) {
            int col = 8 * j + 2 * (lane & 3);
            if (r0 < n)
                out[(size_t)r0 * 32 + (col >> 1)] =
                    __floats2half2_rn(acc[m][j][0], acc[m][j][1]);
            if (r1 < n)
                out[(size_t)r1 * 32 + (col >> 1)] =
                    __floats2half2_rn(acc[m][j][2], acc[m][j][3]);
        }
    }
}

__global__ void __launch_bounds__(128) k_hmma_cat(
    const float* __restrict__ x,
    const float* __restrict__ Wl,
    const float* __restrict__ bl,
    float* __restrict__ out, int n)
{
    __shared__ HSmem sm;
    int t = threadIdx.x;
    int lane = t & 31, warp = t >> 5;
    int rowBase = blockIdx.x * 128;
    float acc[2][8][4] = {};

    for (int i = 0; i < 5; i++) {
        if (i < 2)       load_A32(&sm, x, 128, i * 64, rowBase, n, t);
        else if (i == 2) load_A16(&sm, g_h1, rowBase, n, t);
        else if (i == 3) load_A16(&sm, g_h2, rowBase, n, t);
        else             load_A16(&sm, g_h3, rowBase, n, t);
        load_B(&sm, Wl, i * 64, t);
        __syncthreads();
        hmma_tile(&sm, warp, lane, acc);
        __syncthreads();
    }

    int rw = rowBase + warp * 32;
    #pragma unroll
    for (int m = 0; m < 2; m++) {
        int r0 = rw + m * 16 + (lane >> 2);
        int r1 = r0 + 8;
        #pragma unroll
        for (int j = 0; j < 8; j++) {
            int col = 8 * j + 2 * (lane & 3);
            float b0 = bl[col], b1 = bl[col + 1];
            if (r0 < n)
                *(float2*)&out[(size_t)r0 * 64 + col] =
                    make_float2(acc[m][j][0] + b0, acc[m][j][1] + b1);
            if (r1 < n)
                *(float2*)&out[(size_t)r1 * 64 + col] =
                    make_float2(acc[m][j][2] + b0, acc[m][j][3] + b1);
        }
    }
}

// ===========================================================================
// Aggregation: warp per node, lane = one half2 (2 cols). Unroll x8 with all
// cv loads issued before feature loads (MLP 8 on the random stream).
// ===========================================================================
__global__ void __launch_bounds__(256) k_gather(
    const __half2* __restrict__ hw,
    const float* __restrict__ bias,
    __half2* __restrict__ hout, int n)
{
    int g = blockIdx.x * blockDim.x + threadIdx.x;
    int node = g >> 5;
    int lane = g & 31;
    if (node >= n) return;
    int beg = g_rowptr[node];
    int end = g_rowptr[node + 1];
    float a0 = 0.f, a1 = 0.f;
    int e = beg;
    for (; e + 7 < end; e += 8) {
        int2 cv[8];
        #pragma unroll
        for (int j = 0; j < 8; j++) cv[j] = __ldg(&g_cv[e + j]);
        float2 f[8];
        #pragma unroll
        for (int j = 0; j < 8; j++)
            f[j] = __half22float2(hw[(size_t)cv[j].x * 32 + lane]);
        #pragma unroll
        for (int j = 0; j < 8; j++) {
            float v = __int_as_float(cv[j].y);
            a0 = fmaf(v, f[j].x, a0);
            a1 = fmaf(v, f[j].y, a1);
        }
    }
    for (; e < end; e++) {
        int2 cv = __ldg(&g_cv[e]);
        float2 f = __half22float2(hw[(size_t)cv.x * 32 + lane]);
        float v = __int_as_float(cv.y);
        a0 = fmaf(v, f.x, a0); a1 = fmaf(v, f.y, a1);
    }
    float b0 = bias[2 * lane], b1 = bias[2 * lane + 1];
    hout[(size_t)node * 32 + lane] =
        __floats2half2_rn(fmaxf(a0 + b0, 0.f), fmaxf(a1 + b1, 0.f));
}

// ---------------------------------------------------------------------------
extern "C" void kernel_launch(void* const* d_in, const int* in_sizes, int n_in,
                              void* d_out, int out_size)
{
    const float* x  = (const float*)d_in[0];
    const int*   ei = (const int*)d_in[1];     // int32 edge_index [2, E]
    const float* W0 = (const float*)d_in[2];
    const float* b0 = (const float*)d_in[3];
    const float* W1 = (const float*)d_in[4];
    const float* b1 = (const float*)d_in[5];
    const float* W2 = (const float*)d_in[6];
    const float* b2 = (const float*)d_in[7];
    const float* Wl = (const float*)d_in[8];
    const float* bl = (const float*)d_in[9];
    float* out = (float*)d_out;

    int n = in_sizes[0] / 128;
    int e = in_sizes[1] / 2;
    int nb = (n + 1023) >> 10;

    __half2 *hw_ptr = nullptr, *h1_ptr = nullptr, *h2_ptr = nullptr, *h3_ptr = nullptr;
    cudaGetSymbolAddress((void**)&hw_ptr, g_hw);
    cudaGetSymbolAddress((void**)&h1_ptr, g_h1);
    cudaGetSymbolAddress((void**)&h2_ptr, g_h2);
    cudaGetSymbolAddress((void**)&h3_ptr, g_h3);

    // ---- CSR build ----
    int cth = (e + 1) / 2;
    k_count2<<<(cth + 255) / 256, 256>>>(ei, e);
    k_scan_local<<<nb, 1024>>>(n);
    k_scan_bsums<<<1, 128>>>(nb, n);
    k_scan_add<<<nb, 1024>>>(n);
    k_fill<<<(e + n + 255) / 256, 256>>>(ei, e, n);

    int mma_blocks = (n + 127) / 128;
    int gather_blocks = (n * 32 + 255) / 256;

    // ---- layer 1 ----
    k_hmma_xform<<<mma_blocks, 128>>>(x, nullptr, 128, W0, hw_ptr, n);
    k_gather<<<gather_blocks, 256>>>(hw_ptr, b0, h1_ptr, n);
    // ---- layer 2 ----
    k_hmma_xform<<<mma_blocks, 128>>>(nullptr, h1_ptr, 64, W1, hw_ptr, n);
    k_gather<<<gather_blocks, 256>>>(hw_ptr, b1, h2_ptr, n);
    // ---- layer 3 ----
    k_hmma_xform<<<mma_blocks, 128>>>(nullptr, h2_ptr, 64, W2, hw_ptr, n);
    k_gather<<<gather_blocks, 256>>>(hw_ptr, b2, h3_ptr, n);
    // ---- JK concat + linear ----
    k_hmma_cat<<<mma_blocks, 128>>>(x, Wl, bl, out, n);
}